// round 5
// baseline (speedup 1.0000x reference)
#include <cuda_runtime.h>
#include <cuda_bf16.h>
#include <math.h>

#define LNUM 4
#define D 1024
#define H 16
#define KVH 4
#define HD 64
#define NE 8
#define TOPK 2
#define FF 512
#define NV 32000
#define NB 2
#define NT 1024
#define NTOK (NB*NT)        // 2048
#define NSLOT (NTOK*TOPK)   // 4096
#define EPSV 1e-6f

// ---------------- scratch (static device globals; no allocs) ----------------
__device__ float g_x[NTOK*D];
__device__ float g_xn[NTOK*D];
__device__ float g_q[NTOK*H*HD];
__device__ float g_k[NTOK*KVH*HD];
__device__ float g_v[NTOK*KVH*HD];
__device__ float g_att[NTOK*H*HD];
__device__ float g_gbuf[NSLOT*FF];
__device__ float g_ubuf[NSLOT*FF];
__device__ float g_ybuf[NSLOT*D];
__device__ float g_xmean[NB*D];
__device__ int   g_topk_idx[NTOK*TOPK];
__device__ float g_topk_gate[NTOK*TOPK];
__device__ int   g_count[NE];
__device__ int   g_offset[NE];
__device__ int   g_fill[NE];
__device__ float g_mesum[NE];
__device__ int   g_slot_token[NSLOT];
__device__ int   g_slot_of[NTOK*TOPK];
__device__ float g_aux[1];

// ---------------- embedding ----------------
__global__ void embed_kernel(const int* __restrict__ ids, const float* __restrict__ emb) {
    int n = blockIdx.x;
    int id = ids[n];
    int d = threadIdx.x * 4;
    float4 v = *(const float4*)(emb + (size_t)id * D + d);
    *(float4*)(g_x + (size_t)n * D + d) = v;
}

// ---------------- rmsnorm ----------------
__global__ void rmsnorm_kernel(const float* __restrict__ w,
                               const float* __restrict__ src,
                               float* __restrict__ dst) {
    int n = blockIdx.x, tid = threadIdx.x;
    const float* x = src + (size_t)n * D;
    float ss = 0.f;
    for (int d = tid; d < D; d += 256) { float v = x[d]; ss += v * v; }
    __shared__ float red[256];
    red[tid] = ss; __syncthreads();
    for (int off = 128; off > 0; off >>= 1) {
        if (tid < off) red[tid] += red[tid + off];
        __syncthreads();
    }
    __shared__ float s_scale;
    if (tid == 0) s_scale = rsqrtf(red[0] / (float)D + EPSV);
    __syncthreads();
    float sc = s_scale;
    float* o = dst + (size_t)n * D;
    for (int d = tid; d < D; d += 256) o[d] = w[d] * x[d] * sc;
}

// ---------------- generic SGEMM: C[M,N] = A[M,K] @ B[K,N] (+C if acc) ------
#define BM 128
#define BN 128
#define BKT 8
__global__ void __launch_bounds__(256) gemm_kernel(
    int M, int N, int K,
    const float* __restrict__ A, int lda,
    const float* __restrict__ B, int ldb,
    float* __restrict__ C, int ldc, int accflag)
{
    __shared__ float As[BKT][BM];
    __shared__ float Bs[BKT][BN];
    int bm = blockIdx.y * BM, bn = blockIdx.x * BN;
    int tid = threadIdx.x;
    int tx = tid & 15, ty = tid >> 4;
    int ar = tid >> 1, ac = (tid & 1) * 4;
    int br = tid >> 5, bc = (tid & 31) * 4;
    float acc[8][8];
    #pragma unroll
    for (int i = 0; i < 8; i++)
        #pragma unroll
        for (int j = 0; j < 8; j++) acc[i][j] = 0.f;

    for (int k0 = 0; k0 < K; k0 += BKT) {
        float4 av = make_float4(0.f, 0.f, 0.f, 0.f);
        int grow = bm + ar;
        if (grow < M) av = *(const float4*)(A + (size_t)grow * lda + k0 + ac);
        As[ac + 0][ar] = av.x; As[ac + 1][ar] = av.y;
        As[ac + 2][ar] = av.z; As[ac + 3][ar] = av.w;
        float4 bv = *(const float4*)(B + (size_t)(k0 + br) * ldb + bn + bc);
        *(float4*)&Bs[br][bc] = bv;
        __syncthreads();
        #pragma unroll
        for (int kk = 0; kk < BKT; kk++) {
            float a[8], b[8];
            *(float4*)&a[0] = *(const float4*)&As[kk][ty * 8];
            *(float4*)&a[4] = *(const float4*)&As[kk][ty * 8 + 4];
            *(float4*)&b[0] = *(const float4*)&Bs[kk][tx * 8];
            *(float4*)&b[4] = *(const float4*)&Bs[kk][tx * 8 + 4];
            #pragma unroll
            for (int i = 0; i < 8; i++)
                #pragma unroll
                for (int j = 0; j < 8; j++) acc[i][j] += a[i] * b[j];
        }
        __syncthreads();
    }
    #pragma unroll
    for (int i = 0; i < 8; i++) {
        int row = bm + ty * 8 + i;
        if (row < M) {
            float* cp = C + (size_t)row * ldc + bn + tx * 8;
            if (accflag) {
                #pragma unroll
                for (int j = 0; j < 8; j++) cp[j] += acc[i][j];
            } else {
                *(float4*)cp     = make_float4(acc[i][0], acc[i][1], acc[i][2], acc[i][3]);
                *(float4*)(cp+4) = make_float4(acc[i][4], acc[i][5], acc[i][6], acc[i][7]);
            }
        }
    }
}

// ---------------- MoE expert GEMM (gathered rows, per-expert B, ldb == N) ---
// blockIdx.z = expert. Rows are slots [offset[e], offset[e]+count[e]).
// If use_map: A row index = g_slot_token[slot] (gather); else A row = slot.
__global__ void __launch_bounds__(256) gemm_moe_kernel(
    int N, int K,
    const float* __restrict__ A, int lda, int use_map,
    const float* __restrict__ Bbase, size_t bstride,
    float* __restrict__ C, int ldc)
{
    int e = blockIdx.z;
    int cnt = g_count[e];
    if ((int)(blockIdx.y * BM) >= cnt) return;
    int base = g_offset[e];
    const float* B = Bbase + (size_t)e * bstride;

    __shared__ float As[BKT][BM];
    __shared__ float Bs[BKT][BN];
    int bm = blockIdx.y * BM, bn = blockIdx.x * BN;
    int tid = threadIdx.x;
    int tx = tid & 15, ty = tid >> 4;
    int ar = tid >> 1, ac = (tid & 1) * 4;
    int br = tid >> 5, bc = (tid & 31) * 4;
    float acc[8][8];
    #pragma unroll
    for (int i = 0; i < 8; i++)
        #pragma unroll
        for (int j = 0; j < 8; j++) acc[i][j] = 0.f;

    int mloc = bm + ar;
    int arow = -1;
    if (mloc < cnt) {
        int slot = base + mloc;
        arow = use_map ? g_slot_token[slot] : slot;
    }
    for (int k0 = 0; k0 < K; k0 += BKT) {
        float4 av = make_float4(0.f, 0.f, 0.f, 0.f);
        if (arow >= 0) av = *(const float4*)(A + (size_t)arow * lda + k0 + ac);
        As[ac + 0][ar] = av.x; As[ac + 1][ar] = av.y;
        As[ac + 2][ar] = av.z; As[ac + 3][ar] = av.w;
        float4 bv = *(const float4*)(B + (size_t)(k0 + br) * N + bn + bc);
        *(float4*)&Bs[br][bc] = bv;
        __syncthreads();
        #pragma unroll
        for (int kk = 0; kk < BKT; kk++) {
            float a[8], b[8];
            *(float4*)&a[0] = *(const float4*)&As[kk][ty * 8];
            *(float4*)&a[4] = *(const float4*)&As[kk][ty * 8 + 4];
            *(float4*)&b[0] = *(const float4*)&Bs[kk][tx * 8];
            *(float4*)&b[4] = *(const float4*)&Bs[kk][tx * 8 + 4];
            #pragma unroll
            for (int i = 0; i < 8; i++)
                #pragma unroll
                for (int j = 0; j < 8; j++) acc[i][j] += a[i] * b[j];
        }
        __syncthreads();
    }
    #pragma unroll
    for (int i = 0; i < 8; i++) {
        int m2 = bm + ty * 8 + i;
        if (m2 < cnt) {
            float* cp = C + (size_t)(base + m2) * ldc + bn + tx * 8;
            *(float4*)cp     = make_float4(acc[i][0], acc[i][1], acc[i][2], acc[i][3]);
            *(float4*)(cp+4) = make_float4(acc[i][4], acc[i][5], acc[i][6], acc[i][7]);
        }
    }
}

// ---------------- RoPE (in-place on g_q, g_k) ----------------
__global__ void rope_kernel() {
    int n = blockIdx.x;
    int pos = n % NT;
    int tid = threadIdx.x;
    const int QW = H * (HD / 2);         // 512
    const int TW = (H + KVH) * (HD / 2); // 640
    for (int w = tid; w < TW; w += 256) {
        float* bp; int i;
        if (w < QW) {
            int hh = w >> 5; i = w & 31;
            bp = g_q + (size_t)n * (H * HD) + hh * HD;
        } else {
            int w2 = w - QW;
            int hh = w2 >> 5; i = w2 & 31;
            bp = g_k + (size_t)n * (KVH * HD) + hh * HD;
        }
        // inv = ROPE_BASE^(-2i/64); ln(1e6) = 13.815510557964274
        float inv = expf(-(2.0f * (float)i / (float)HD) * 13.815510557964274f);
        float s, c;
        sincosf((float)pos * inv, &s, &c);
        float x1 = bp[2 * i], x2 = bp[2 * i + 1];
        bp[2 * i]     = x1 * c - x2 * s;
        bp[2 * i + 1] = x1 * s + x2 * c;
    }
}

// ---------------- flash attention (causal, GQA) ----------------
// One thread per query row; 64-row K/V tiles. K and V share one smem buffer
// (loaded sequentially per tile) to stay under the 48KB static smem limit.
__global__ void __launch_bounds__(64) attn_kernel() {
    int bh = blockIdx.x;
    int b = bh / H, h = bh % H;
    int qb = blockIdx.y;
    int tid = threadIdx.x;
    int kvh = h / (H / KVH);
    __shared__ float KV[64 * 64];      // 16 KB, reused for K then V
    __shared__ float Ss[64 * 65];      // 16.6 KB, padded rows (conflict-free)

    int qi = qb * 64 + tid;
    const float* qptr = g_q + (size_t)(b * NT + qi) * (H * HD) + h * HD;
    float qreg[64], acc[64];
    #pragma unroll
    for (int d = 0; d < 64; d += 4) {
        float4 v = *(const float4*)(qptr + d);
        qreg[d] = v.x; qreg[d+1] = v.y; qreg[d+2] = v.z; qreg[d+3] = v.w;
    }
    #pragma unroll
    for (int d = 0; d < 64; d++) acc[d] = 0.f;
    float m = -1e30f, lsum = 0.f;

    int ntile = qb + 1;
    for (int t0 = 0; t0 < ntile; t0++) {
        int k0 = t0 * 64;
        // --- load K tile ---
        for (int idx = tid; idx < 64 * 16; idx += 64) {
            int r = idx >> 4, c4 = (idx & 15) << 2;
            size_t kbase = (size_t)(b * NT + k0 + r) * (KVH * HD) + kvh * HD + c4;
            *(float4*)&KV[r * 64 + c4] = *(const float4*)(g_k + kbase);
        }
        __syncthreads();
        // --- scores ---
        float tmax = -1e30f;
        for (int j = 0; j < 64; j++) {
            float s = 0.f;
            const float* kr = &KV[j * 64];
            #pragma unroll
            for (int d = 0; d < 64; d += 4) {
                float4 kv = *(const float4*)(kr + d);
                s += qreg[d] * kv.x + qreg[d+1] * kv.y + qreg[d+2] * kv.z + qreg[d+3] * kv.w;
            }
            s *= 0.125f;
            if (k0 + j > qi) s = -1e30f;
            Ss[tid * 65 + j] = s;
            tmax = fmaxf(tmax, s);
        }
        __syncthreads();   // all threads done reading K before overwrite
        // --- load V tile into same buffer ---
        for (int idx = tid; idx < 64 * 16; idx += 64) {
            int r = idx >> 4, c4 = (idx & 15) << 2;
            size_t vbase = (size_t)(b * NT + k0 + r) * (KVH * HD) + kvh * HD + c4;
            *(float4*)&KV[r * 64 + c4] = *(const float4*)(g_v + vbase);
        }
        __syncthreads();
        // --- online softmax update + PV accumulate ---
        float mnew = fmaxf(m, tmax);
        float corr = __expf(m - mnew);
        lsum *= corr;
        #pragma unroll
        for (int d = 0; d < 64; d++) acc[d] *= corr;
        for (int j = 0; j < 64; j++) {
            float p = __expf(Ss[tid * 65 + j] - mnew);
            lsum += p;
            const float* vr = &KV[j * 64];
            #pragma unroll
            for (int d = 0; d < 64; d += 4) {
                float4 vv = *(const float4*)(vr + d);
                acc[d]   += p * vv.x; acc[d+1] += p * vv.y;
                acc[d+2] += p * vv.z; acc[d+3] += p * vv.w;
            }
        }
        m = mnew;
        __syncthreads();   // done reading V before next tile's K load
    }
    float inv = 1.f / lsum;
    float* op = g_att + (size_t)(b * NT + qi) * (H * HD) + h * HD;
    #pragma unroll
    for (int d = 0; d < 64; d += 4) {
        float4 o = make_float4(acc[d]*inv, acc[d+1]*inv, acc[d+2]*inv, acc[d+3]*inv);
        *(float4*)(op + d) = o;
    }
}

// ---------------- router + top-2 + aux stats ----------------
__global__ void zero_counters(int zero_aux) {
    int t = threadIdx.x;
    if (t < NE) { g_count[t] = 0; g_mesum[t] = 0.f; }
    if (t == 0 && zero_aux) g_aux[0] = 0.f;
}

__global__ void router_kernel(const float* __restrict__ rw) {
    int n = blockIdx.x, tid = threadIdx.x;
    __shared__ float red[NE][257];
    float acc[NE];
    #pragma unroll
    for (int e = 0; e < NE; e++) acc[e] = 0.f;
    const float* x = g_xn + (size_t)n * D;
    for (int d = tid; d < D; d += 256) {
        float xv = x[d];
        const float* r = rw + (size_t)d * NE;
        #pragma unroll
        for (int e = 0; e < NE; e++) acc[e] += xv * r[e];
    }
    #pragma unroll
    for (int e = 0; e < NE; e++) red[e][tid] = acc[e];
    __syncthreads();
    for (int off = 128; off > 0; off >>= 1) {
        if (tid < off) {
            #pragma unroll
            for (int e = 0; e < NE; e++) red[e][tid] += red[e][tid + off];
        }
        __syncthreads();
    }
    if (tid == 0) {
        float lg[NE], p[NE];
        float mx = -1e30f;
        #pragma unroll
        for (int e = 0; e < NE; e++) { lg[e] = red[e][0]; mx = fmaxf(mx, lg[e]); }
        float sum = 0.f;
        #pragma unroll
        for (int e = 0; e < NE; e++) { p[e] = __expf(lg[e] - mx); sum += p[e]; }
        #pragma unroll
        for (int e = 0; e < NE; e++) p[e] /= sum;
        #pragma unroll
        for (int e = 0; e < NE; e++) atomicAdd(&g_mesum[e], p[e]);
        int i0 = 0;
        #pragma unroll
        for (int e = 1; e < NE; e++) if (p[e] > p[i0]) i0 = e;
        int i1 = (i0 == 0) ? 1 : 0;
        #pragma unroll
        for (int e = 0; e < NE; e++) if (e != i0 && p[e] > p[i1]) i1 = e;
        float g0 = p[i0], g1 = p[i1], gs = g0 + g1;
        g_topk_idx[n * 2] = i0; g_topk_idx[n * 2 + 1] = i1;
        g_topk_gate[n * 2] = g0 / gs; g_topk_gate[n * 2 + 1] = g1 / gs;
        atomicAdd(&g_count[i0], 1);
        atomicAdd(&g_count[i1], 1);
    }
}

__global__ void scan_aux_kernel() {
    if (threadIdx.x == 0) {
        int off = 0;
        float aux = 0.f;
        for (int e = 0; e < NE; e++) {
            g_offset[e] = off;
            off += g_count[e];
            float me = g_mesum[e] / (float)NTOK;
            float ce = (float)g_count[e] / (float)(NTOK * TOPK);
            aux += me * ce;
            g_fill[e] = 0;
        }
        g_aux[0] += (float)NE * aux;
    }
}

__global__ void scatter_kernel() {
    int n = blockIdx.x * blockDim.x + threadIdx.x;
    if (n >= NTOK) return;
    #pragma unroll
    for (int k = 0; k < TOPK; k++) {
        int e = g_topk_idx[n * 2 + k];
        int pos = atomicAdd(&g_fill[e], 1);
        int s = g_offset[e] + pos;
        g_slot_token[s] = n;
        g_slot_of[n * 2 + k] = s;
    }
}

__global__ void silu_mul_kernel() {
    size_t i = ((size_t)blockIdx.x * 256 + threadIdx.x) * 4;
    float4 g = *(float4*)(g_gbuf + i);
    float4 u = *(float4*)(g_ubuf + i);
    g.x = g.x / (1.f + __expf(-g.x)) * u.x;
    g.y = g.y / (1.f + __expf(-g.y)) * u.y;
    g.z = g.z / (1.f + __expf(-g.z)) * u.z;
    g.w = g.w / (1.f + __expf(-g.w)) * u.w;
    *(float4*)(g_gbuf + i) = g;
}

__global__ void combine_kernel() {
    int n = blockIdx.x, tid = threadIdx.x;
    int s0 = g_slot_of[n * 2], s1 = g_slot_of[n * 2 + 1];
    float w0 = g_topk_gate[n * 2], w1 = g_topk_gate[n * 2 + 1];
    int d = tid * 4;
    float4 a  = *(float4*)(g_x + (size_t)n * D + d);
    float4 y0 = *(const float4*)(g_ybuf + (size_t)s0 * D + d);
    float4 y1 = *(const float4*)(g_ybuf + (size_t)s1 * D + d);
    a.x += w0 * y0.x + w1 * y1.x;
    a.y += w0 * y0.y + w1 * y1.y;
    a.z += w0 * y0.z + w1 * y1.z;
    a.w += w0 * y0.w + w1 * y1.w;
    *(float4*)(g_x + (size_t)n * D + d) = a;
}

// ---------------- final heads ----------------
__global__ void mean_kernel() {
    int i = blockIdx.x * 256 + threadIdx.x;  // 0 .. NB*D-1
    int b = i / D, d = i % D;
    float s = 0.f;
    for (int t = 0; t < NT; t++) s += g_xn[(size_t)(b * NT + t) * D + d];
    g_xmean[i] = s / (float)NT;
}

#define TASKN 10
#define EVALN 5
__global__ void heads_kernel(const float* __restrict__ task_w, const float* __restrict__ task_b,
                             const float* __restrict__ eval_w, const float* __restrict__ eval_b,
                             float* __restrict__ out) {
    const size_t LOG = (size_t)NTOK * NV;
    int o = blockIdx.x, tid = threadIdx.x;
    if (o == NB * TASKN + NB * EVALN) {
        if (tid == 0) out[LOG + NB * TASKN + NB * EVALN] = g_aux[0];
        return;
    }
    const float* x; const float* w; float bias; size_t oi; int stride;
    if (o < NB * TASKN) {
        int b = o / TASKN, j = o % TASKN;
        x = g_xn + (size_t)(b * NT) * D;
        w = task_w + j; stride = TASKN; bias = task_b[j];
        oi = LOG + b * TASKN + j;
    } else {
        int o2 = o - NB * TASKN;
        int b = o2 / EVALN, j = o2 % EVALN;
        x = g_xmean + (size_t)b * D;
        w = eval_w + j; stride = EVALN; bias = eval_b[j];
        oi = LOG + NB * TASKN + b * EVALN + j;
    }
    float s = 0.f;
    for (int d = tid; d < D; d += 256) s += x[d] * w[(size_t)d * stride];
    __shared__ float red[256];
    red[tid] = s; __syncthreads();
    for (int off = 128; off > 0; off >>= 1) {
        if (tid < off) red[tid] += red[tid + off];
        __syncthreads();
    }
    if (tid == 0) out[oi] = red[0] + bias;
}

// ---------------- launch ----------------
extern "C" void kernel_launch(void* const* d_in, const int* in_sizes, int n_in,
                              void* d_out, int out_size) {
    const int*   ids    = (const int*)  d_in[0];
    const float* emb    = (const float*)d_in[1];
    const float* wq     = (const float*)d_in[2];
    const float* wk     = (const float*)d_in[3];
    const float* wv     = (const float*)d_in[4];
    const float* wo     = (const float*)d_in[5];
    const float* n1     = (const float*)d_in[6];
    const float* n2     = (const float*)d_in[7];
    const float* rw     = (const float*)d_in[8];
    const float* wgte   = (const float*)d_in[9];
    const float* wup    = (const float*)d_in[10];
    const float* wdn    = (const float*)d_in[11];
    const float* nf     = (const float*)d_in[12];
    const float* lmw    = (const float*)d_in[13];
    const float* tw     = (const float*)d_in[14];
    const float* tb     = (const float*)d_in[15];
    const float* ew     = (const float*)d_in[16];
    const float* eb     = (const float*)d_in[17];
    float* out = (float*)d_out;

    float *px, *pxn, *pq, *pk, *pv, *patt, *pg, *pu, *py;
    cudaGetSymbolAddress((void**)&px,   g_x);
    cudaGetSymbolAddress((void**)&pxn,  g_xn);
    cudaGetSymbolAddress((void**)&pq,   g_q);
    cudaGetSymbolAddress((void**)&pk,   g_k);
    cudaGetSymbolAddress((void**)&pv,   g_v);
    cudaGetSymbolAddress((void**)&patt, g_att);
    cudaGetSymbolAddress((void**)&pg,   g_gbuf);
    cudaGetSymbolAddress((void**)&pu,   g_ubuf);
    cudaGetSymbolAddress((void**)&py,   g_ybuf);

    embed_kernel<<<NTOK, 256>>>(ids, emb);
    zero_counters<<<1, 32>>>(1);

    for (int l = 0; l < LNUM; l++) {
        rmsnorm_kernel<<<NTOK, 256>>>(n1 + (size_t)l * D, px, pxn);
        gemm_kernel<<<dim3(8, 16), 256>>>(NTOK, 1024, 1024, pxn, 1024,
                                          wq + (size_t)l * D * 1024, 1024, pq, 1024, 0);
        gemm_kernel<<<dim3(2, 16), 256>>>(NTOK, 256, 1024, pxn, 1024,
                                          wk + (size_t)l * D * 256, 256, pk, 256, 0);
        gemm_kernel<<<dim3(2, 16), 256>>>(NTOK, 256, 1024, pxn, 1024,
                                          wv + (size_t)l * D * 256, 256, pv, 256, 0);
        rope_kernel<<<NTOK, 256>>>();
        attn_kernel<<<dim3(NB * H, NT / 64), 64>>>();
        gemm_kernel<<<dim3(8, 16), 256>>>(NTOK, 1024, 1024, patt, 1024,
                                          wo + (size_t)l * 1024 * D, 1024, px, 1024, 1);

        rmsnorm_kernel<<<NTOK, 256>>>(n2 + (size_t)l * D, px, pxn);
        zero_counters<<<1, 32>>>(0);
        router_kernel<<<NTOK, 256>>>(rw + (size_t)l * D * NE);
        scan_aux_kernel<<<1, 32>>>();
        scatter_kernel<<<NTOK / 256, 256>>>();

        gemm_moe_kernel<<<dim3(FF / 128, 16, NE), 256>>>(
            FF, D, pxn, D, 1, wgte + (size_t)l * NE * D * FF, (size_t)D * FF, pg, FF);
        gemm_moe_kernel<<<dim3(FF / 128, 16, NE), 256>>>(
            FF, D, pxn, D, 1, wup + (size_t)l * NE * D * FF, (size_t)D * FF, pu, FF);
        silu_mul_kernel<<<(NSLOT * FF) / 1024, 256>>>();
        gemm_moe_kernel<<<dim3(D / 128, 16, NE), 256>>>(
            D, FF, pg, FF, 0, wdn + (size_t)l * NE * FF * D, (size_t)FF * D, py, D);
        combine_kernel<<<NTOK, 256>>>();
    }

    rmsnorm_kernel<<<NTOK, 256>>>(nf, px, pxn);
    gemm_kernel<<<dim3(NV / 128, 16), 256>>>(NTOK, NV, 1024, pxn, 1024, lmw, NV, out, NV, 0);
    mean_kernel<<<(NB * D) / 256, 256>>>();
    heads_kernel<<<NB * TASKN + NB * EVALN + 1, 256>>>(tw, tb, ew, eb, out);
}